// round 4
// baseline (speedup 1.0000x reference)
#include <cuda_runtime.h>
#include <stdint.h>
#include <stddef.h>

// ---------------- problem constants ----------------
#define NT      256      // threads per block
#define NG      32       // batch groups (4 rows each)
#define DEPTH   8        // ring depth (power of 2)
#define NB      128      // batch
#define NTIME   4096     // timesteps
#define NF      64       // input features

// layer dims
#define H0 77
#define K0 141
#define KP0 148
#define H1 51
#define K1 128
#define KP1 132
#define H2 128
#define K2 179
#define KP2 180
#define H2H 64

// smem float counts per stage: weights + biases + z + acc
#define SMF0 (4*H0*KP0 + 4*H0 + 4*KP0 + 16*H0)   // 47716
#define SMF1 (4*H1*KP1 + 4*H1 + 4*KP1 + 16*H1)
#define SMF2 (4*H2H*KP2 + 4*H2H + 4*KP2 + 16*H2H) // 48080
#define SMEM_BYTES (SMF2 * 4)                     // 192320 (>= all stages)

struct Params {
    const float* x;
    const float* h0;
    const float* m[3];
    const float* W1[3]; const float* W2[3]; const float* Wa[3]; const float* Wb[3];
    const float* b1[3]; const float* b2[3]; const float* ba[3]; const float* bb[3];
    float* out;
    int out_size;
};

// ---------------- global scratch (static __device__ — allowed) ----------------
struct alignas(128) Ctr { unsigned v; unsigned pad_[31]; };

__device__ Ctr g_p0[NG], g_c01[NG];
__device__ Ctr g_p1[NG], g_c12a[NG], g_c12b[NG];
__device__ Ctr g_pA[NG], g_pB[NG], g_cAB[NG], g_cBA[NG];

__device__ float g_ring01[NG][DEPTH][4*80];   // stage0 -> stage1 (77/row, pad 80)
__device__ float g_ring12[NG][DEPTH][4*56];   // stage1 -> stage2a/2b (51/row, pad 56)
__device__ float g_ringA[NG][DEPTH][4*64];    // 2a -> 2b (h2 low half)
__device__ float g_ringB[NG][DEPTH][4*64];    // 2b -> 2a (h2 high half)

// ---------------- sync helpers ----------------
__device__ __forceinline__ unsigned ld_acq(const unsigned* p) {
    unsigned v;
    asm volatile("ld.acquire.gpu.u32 %0, [%1];" : "=r"(v) : "l"(p) : "memory");
    return v;
}
__device__ __forceinline__ void st_rel(unsigned* p, unsigned v) {
    asm volatile("st.release.gpu.u32 [%0], %1;" :: "l"(p), "r"(v) : "memory");
}
__device__ __forceinline__ void wait_ge(const unsigned* p, unsigned tgt) {
    unsigned it = 0;
    while (ld_acq(p) < tgt) {
        if (++it > 32u) __nanosleep(64);
    }
}

// ---------------- math ----------------
__device__ __forceinline__ float cfc_h(float a1, float a2, float aa, float ab) {
    float ff1 = tanhf(a1);
    float ff2 = tanhf(a2);
    float ti  = 0.5f * tanhf(0.5f * (aa + ab)) + 0.5f;   // sigmoid(aa+ab)
    return ff1 + ti * (ff2 - ff1);
}

// ---------------- premask weights into SMEM ----------------
template<int HLOC, int K, int KP>
__device__ void load_weights(float* sW, float* sB, const Params& p, int l, int rowoff, int tid) {
    const float* Ws[4] = { p.W1[l], p.W2[l], p.Wa[l], p.Wb[l] };
    const float* Bs[4] = { p.b1[l], p.b2[l], p.ba[l], p.bb[l] };
    const float* M = p.m[l];
    for (int mat = 0; mat < 4; ++mat) {
        const float* W = Ws[mat];
        for (int idx = tid; idx < HLOC * KP; idx += NT) {
            int j = idx / KP;
            int k = idx - j * KP;
            float v = 0.0f;
            if (k < K) {
                int gi = (rowoff + j) * K + k;
                v = W[gi] * M[gi];
            }
            sW[mat * HLOC * KP + idx] = v;
        }
        for (int j = tid; j < HLOC; j += NT)
            sB[mat * HLOC + j] = Bs[mat][rowoff + j];
    }
}

// ---------------- core matvec: 4 matrices x 4 rows ----------------
template<int HLOC, int KP>
__device__ __forceinline__ void matvec(const float* __restrict__ sW,
                                       const float* __restrict__ sB,
                                       const float* __restrict__ sZ,
                                       float* __restrict__ sAcc, int tid) {
    for (int idx = tid; idx < 4 * HLOC; idx += NT) {
        int m = idx / HLOC;
        int j = idx - m * HLOC;
        const float* w = sW + idx * KP;
        float a0 = 0.f, a1 = 0.f, a2 = 0.f, a3 = 0.f;
        #pragma unroll 4
        for (int k = 0; k < KP; k += 4) {
            float4 wv = *reinterpret_cast<const float4*>(w + k);
            float4 z0 = *reinterpret_cast<const float4*>(sZ + 0 * KP + k);
            float4 z1 = *reinterpret_cast<const float4*>(sZ + 1 * KP + k);
            float4 z2 = *reinterpret_cast<const float4*>(sZ + 2 * KP + k);
            float4 z3 = *reinterpret_cast<const float4*>(sZ + 3 * KP + k);
            a0 = fmaf(wv.x, z0.x, a0); a0 = fmaf(wv.y, z0.y, a0);
            a0 = fmaf(wv.z, z0.z, a0); a0 = fmaf(wv.w, z0.w, a0);
            a1 = fmaf(wv.x, z1.x, a1); a1 = fmaf(wv.y, z1.y, a1);
            a1 = fmaf(wv.z, z1.z, a1); a1 = fmaf(wv.w, z1.w, a1);
            a2 = fmaf(wv.x, z2.x, a2); a2 = fmaf(wv.y, z2.y, a2);
            a2 = fmaf(wv.z, z2.z, a2); a2 = fmaf(wv.w, z2.w, a2);
            a3 = fmaf(wv.x, z3.x, a3); a3 = fmaf(wv.y, z3.y, a3);
            a3 = fmaf(wv.z, z3.z, a3); a3 = fmaf(wv.w, z3.w, a3);
        }
        float bias = sB[idx];
        sAcc[(m * 4 + 0) * HLOC + j] = a0 + bias;
        sAcc[(m * 4 + 1) * HLOC + j] = a1 + bias;
        sAcc[(m * 4 + 2) * HLOC + j] = a2 + bias;
        sAcc[(m * 4 + 3) * HLOC + j] = a3 + bias;
    }
}

// ---------------- stage 0: layer 0 (x -> h0new) ----------------
__device__ void run_stage0(const Params& p, int g, float* sm, int tid) {
    float* sW   = sm;
    float* sB   = sW + 4 * H0 * KP0;
    float* sZ   = sB + 4 * H0;
    float* sAcc = sZ + 4 * KP0;

    load_weights<H0, K0, KP0>(sW, sB, p, 0, 0, tid);
    for (int idx = tid; idx < 4 * KP0; idx += NT) sZ[idx] = 0.f;
    __syncthreads();
    for (int idx = tid; idx < 4 * H0; idx += NT) {
        int r = idx / H0, j = idx - r * H0;
        sZ[r * KP0 + NF + j] = p.h0[(size_t)(g * 4 + r) * 256 + j];
    }
    __syncthreads();

    const int xr = tid >> 6, xi = tid & 63;
    const float* xb = p.x + (size_t)(g * 4 + xr) * NTIME * NF + xi;
    float xv = xb[0];

    unsigned* c01 = &g_c01[g].v;
    unsigned* p0  = &g_p0[g].v;

    for (int t = 0; t < NTIME; ++t) {
        if (tid == 0 && t >= DEPTH) wait_ge(c01, (unsigned)(t + 1 - DEPTH));
        __syncthreads();
        sZ[xr * KP0 + xi] = xv;
        if (t + 1 < NTIME) xv = xb[(size_t)(t + 1) * NF];
        __syncthreads();
        matvec<H0, KP0>(sW, sB, sZ, sAcc, tid);
        __syncthreads();
        float* slot = g_ring01[g][t & (DEPTH - 1)];
        for (int idx = tid; idx < 4 * H0; idx += NT) {
            int r = idx / H0, j = idx - r * H0;
            float h = cfc_h(sAcc[(0 * 4 + r) * H0 + j], sAcc[(1 * 4 + r) * H0 + j],
                            sAcc[(2 * 4 + r) * H0 + j], sAcc[(3 * 4 + r) * H0 + j]);
            sZ[r * KP0 + NF + j] = h;
            slot[r * 80 + j] = h;
        }
        __syncthreads();
        if (tid == 0) { __threadfence(); st_rel(p0, (unsigned)(t + 1)); }
    }
    if (p.out_size >= NB * NTIME * 128 + NB * 256) {
        float* hx = p.out + (size_t)NB * NTIME * 128;
        for (int idx = tid; idx < 4 * H0; idx += NT) {
            int r = idx / H0, j = idx - r * H0;
            hx[(size_t)(g * 4 + r) * 256 + j] = sZ[r * KP0 + NF + j];
        }
    }
}

// ---------------- stage 1: layer 1 ----------------
__device__ void run_stage1(const Params& p, int g, float* sm, int tid) {
    float* sW   = sm;
    float* sB   = sW + 4 * H1 * KP1;
    float* sZ   = sB + 4 * H1;
    float* sAcc = sZ + 4 * KP1;

    load_weights<H1, K1, KP1>(sW, sB, p, 1, 0, tid);
    for (int idx = tid; idx < 4 * KP1; idx += NT) sZ[idx] = 0.f;
    __syncthreads();
    for (int idx = tid; idx < 4 * H1; idx += NT) {
        int r = idx / H1, j = idx - r * H1;
        sZ[r * KP1 + H0 + j] = p.h0[(size_t)(g * 4 + r) * 256 + H0 + j];
    }
    __syncthreads();

    unsigned* p0   = &g_p0[g].v;
    unsigned* c01  = &g_c01[g].v;
    unsigned* p1   = &g_p1[g].v;
    unsigned* c12a = &g_c12a[g].v;
    unsigned* c12b = &g_c12b[g].v;

    for (int t = 0; t < NTIME; ++t) {
        if (tid == 0) {
            wait_ge(p0, (unsigned)(t + 1));
            if (t >= DEPTH) {
                wait_ge(c12a, (unsigned)(t + 1 - DEPTH));
                wait_ge(c12b, (unsigned)(t + 1 - DEPTH));
            }
        }
        __syncthreads();
        const float* islot = g_ring01[g][t & (DEPTH - 1)];
        for (int idx = tid; idx < 4 * H0; idx += NT) {
            int r = idx / H0, j = idx - r * H0;
            sZ[r * KP1 + j] = __ldcg(islot + r * 80 + j);
        }
        __syncthreads();
        if (tid == 0) { __threadfence(); st_rel(c01, (unsigned)(t + 1)); }
        matvec<H1, KP1>(sW, sB, sZ, sAcc, tid);
        __syncthreads();
        float* oslot = g_ring12[g][t & (DEPTH - 1)];
        for (int idx = tid; idx < 4 * H1; idx += NT) {
            int r = idx / H1, j = idx - r * H1;
            float h = cfc_h(sAcc[(0 * 4 + r) * H1 + j], sAcc[(1 * 4 + r) * H1 + j],
                            sAcc[(2 * 4 + r) * H1 + j], sAcc[(3 * 4 + r) * H1 + j]);
            sZ[r * KP1 + H0 + j] = h;
            oslot[r * 56 + j] = h;
        }
        __syncthreads();
        if (tid == 0) { __threadfence(); st_rel(p1, (unsigned)(t + 1)); }
    }
    if (p.out_size >= NB * NTIME * 128 + NB * 256) {
        float* hx = p.out + (size_t)NB * NTIME * 128;
        for (int idx = tid; idx < 4 * H1; idx += NT) {
            int r = idx / H1, j = idx - r * H1;
            hx[(size_t)(g * 4 + r) * 256 + H0 + j] = sZ[r * KP1 + H0 + j];
        }
    }
}

// ---------------- stage 2: layer 2 half (HALF = 0 or 1) ----------------
template<int HALF>
__device__ void run_stage2(const Params& p, int g, float* sm, int tid) {
    float* sW   = sm;
    float* sB   = sW + 4 * H2H * KP2;
    float* sZ   = sB + 4 * H2H;
    float* sAcc = sZ + 4 * KP2;

    const int IN = H1;                 // 51 input features
    const int zoff  = IN + HALF * 64;        // own half position in z
    const int zpeer = IN + (1 - HALF) * 64;  // peer half position in z

    load_weights<H2H, K2, KP2>(sW, sB, p, 2, HALF * 64, tid);
    for (int idx = tid; idx < 4 * KP2; idx += NT) sZ[idx] = 0.f;
    __syncthreads();
    for (int idx = tid; idx < 4 * H2; idx += NT) {
        int r = idx >> 7, u = idx & 127;
        sZ[r * KP2 + IN + u] = p.h0[(size_t)(g * 4 + r) * 256 + 128 + u];
    }
    __syncthreads();

    unsigned* p1       = &g_p1[g].v;
    unsigned* cIn      = HALF ? &g_c12b[g].v : &g_c12a[g].v;
    unsigned* pOwn     = HALF ? &g_pB[g].v   : &g_pA[g].v;
    unsigned* pPeer    = HALF ? &g_pA[g].v   : &g_pB[g].v;
    unsigned* cOwnRing = HALF ? &g_cBA[g].v  : &g_cAB[g].v;  // peer consumed my ring
    unsigned* cPeerRing= HALF ? &g_cAB[g].v  : &g_cBA[g].v;  // I consumed peer ring
    float (*ringOwn)[4*64]  = HALF ? g_ringB[g] : g_ringA[g];
    float (*ringPeer)[4*64] = HALF ? g_ringA[g] : g_ringB[g];

    const int r2 = tid >> 6, j2 = tid & 63;  // NT == 256 == 4*64 exactly

    for (int t = 0; t < NTIME; ++t) {
        if (tid == 0) {
            wait_ge(p1, (unsigned)(t + 1));
            if (t >= 1) wait_ge(pPeer, (unsigned)t);
            if (t >= DEPTH) wait_ge(cOwnRing, (unsigned)(t + 1 - DEPTH));
        }
        __syncthreads();
        const float* islot = g_ring12[g][t & (DEPTH - 1)];
        for (int idx = tid; idx < 4 * IN; idx += NT) {
            int r = idx / IN, j = idx - r * IN;
            sZ[r * KP2 + j] = __ldcg(islot + r * 56 + j);
        }
        if (t >= 1) {
            const float* ps = ringPeer[(t - 1) & (DEPTH - 1)];
            sZ[r2 * KP2 + zpeer + j2] = __ldcg(ps + r2 * 64 + j2);
        }
        __syncthreads();
        if (tid == 0) {
            __threadfence();
            st_rel(cIn, (unsigned)(t + 1));
            if (t >= 1) st_rel(cPeerRing, (unsigned)t);
        }
        matvec<H2H, KP2>(sW, sB, sZ, sAcc, tid);
        __syncthreads();
        {
            float* os = ringOwn[t & (DEPTH - 1)];
            float h = cfc_h(sAcc[(0 * 4 + r2) * H2H + j2], sAcc[(1 * 4 + r2) * H2H + j2],
                            sAcc[(2 * 4 + r2) * H2H + j2], sAcc[(3 * 4 + r2) * H2H + j2]);
            sZ[r2 * KP2 + zoff + j2] = h;
            os[r2 * 64 + j2] = h;
            p.out[(size_t)(g * 4 + r2) * NTIME * 128 + (size_t)t * 128 + HALF * 64 + j2] = h;
        }
        __syncthreads();
        if (tid == 0) { __threadfence(); st_rel(pOwn, (unsigned)(t + 1)); }
    }
    if (p.out_size >= NB * NTIME * 128 + NB * 256) {
        float* hx = p.out + (size_t)NB * NTIME * 128;
        hx[(size_t)(g * 4 + r2) * 256 + 128 + HALF * 64 + j2] = sZ[r2 * KP2 + zoff + j2];
    }
}

// ---------------- kernels ----------------
__global__ void cfc_init_ctrs() {
    int i = threadIdx.x;
    if (i < NG) {
        g_p0[i].v = 0;  g_c01[i].v = 0;
        g_p1[i].v = 0;  g_c12a[i].v = 0; g_c12b[i].v = 0;
        g_pA[i].v = 0;  g_pB[i].v = 0;   g_cAB[i].v = 0; g_cBA[i].v = 0;
    }
}

__global__ void __launch_bounds__(NT, 1) cfc_kernel(Params p) {
    extern __shared__ float sm[];
    const int stage = blockIdx.x & 3;
    const int g     = blockIdx.x >> 2;
    const int tid   = threadIdx.x;
    if      (stage == 0) run_stage0(p, g, sm, tid);
    else if (stage == 1) run_stage1(p, g, sm, tid);
    else if (stage == 2) run_stage2<0>(p, g, sm, tid);
    else                 run_stage2<1>(p, g, sm, tid);
}

// ---------------- host launch ----------------
extern "C" void kernel_launch(void* const* d_in, const int* in_sizes, int n_in,
                              void* d_out, int out_size) {
    Params p;
    p.x  = (const float*)d_in[0];
    p.h0 = (const float*)d_in[1];
    // Input ordering: dict order (m,W1,W2,Wa,Wb,b1,b2,ba,bb) vs reference-signature
    // order (m,W1,b1,W2,b2,Wa,ba,Wb,bb). Detect via in_sizes[4]:
    // dict -> W2_0 (10857 elems), sig -> b2_0 (77 elems).
    bool sig_order = (n_in > 4 && in_sizes[4] == 77);
    for (int l = 0; l < 3; ++l) {
        int b = 2 + 9 * l;
        p.m[l] = (const float*)d_in[b];
        if (!sig_order) {
            p.W1[l] = (const float*)d_in[b + 1];
            p.W2[l] = (const float*)d_in[b + 2];
            p.Wa[l] = (const float*)d_in[b + 3];
            p.Wb[l] = (const float*)d_in[b + 4];
            p.b1[l] = (const float*)d_in[b + 5];
            p.b2[l] = (const float*)d_in[b + 6];
            p.ba[l] = (const float*)d_in[b + 7];
            p.bb[l] = (const float*)d_in[b + 8];
        } else {
            p.W1[l] = (const float*)d_in[b + 1];
            p.b1[l] = (const float*)d_in[b + 2];
            p.W2[l] = (const float*)d_in[b + 3];
            p.b2[l] = (const float*)d_in[b + 4];
            p.Wa[l] = (const float*)d_in[b + 5];
            p.ba[l] = (const float*)d_in[b + 6];
            p.Wb[l] = (const float*)d_in[b + 7];
            p.bb[l] = (const float*)d_in[b + 8];
        }
    }
    p.out = (float*)d_out;
    p.out_size = out_size;

    cudaFuncSetAttribute(cfc_kernel, cudaFuncAttributeMaxDynamicSharedMemorySize, SMEM_BYTES);
    cfc_init_ctrs<<<1, 32>>>();
    cfc_kernel<<<4 * NG, NT, SMEM_BYTES>>>(p);
}

// round 5
// speedup vs baseline: 1.0585x; 1.0585x over previous
#include <cuda_runtime.h>
#include <stdint.h>
#include <stddef.h>

// ---------------- problem constants ----------------
#define NT      256
#define NG      32
#define DEPTH   8
#define NB      128
#define NTIME   4096
#define NF      64

#define H0 77
#define K0 141
#define KP0 148
#define H1 51
#define K1 128
#define KP1 132
#define H2 128
#define K2 179
#define KP2 180
#define H2H 64

// ---- shared memory layout (bytes) ----
// [0,512)    : flags (flag i at byte i*32, as u32)
// [512,15872): ring region
//    rank1: ring01  = DEPTH slots * 320 floats   (slot s at 512 + s*320*4)
//    rank2/3: ring12 = DEPTH * 224 floats at 512; ringPeer = DEPTH * 256 floats at 7680
// [15872, ..): stage area (weights, biases, z, acc) max 48080 floats
#define FLAG_BYTE(i)   ((i) * 32)
#define RING_BYTE      512
#define RINGP_BYTE     (512 + DEPTH * 224 * 4)     // 7680
#define STAGE_F        3968                         // float index of stage area
#define STAGE_MAXF     48080
#define SMEM_BYTES     (15872 + STAGE_MAXF * 4)     // 208192

struct Params {
    const float* x;
    const float* h0;
    const float* m[3];
    const float* W1[3]; const float* W2[3]; const float* Wa[3]; const float* Wb[3];
    const float* b1[3]; const float* b2[3]; const float* ba[3]; const float* bb[3];
    float* out;
    int out_size;
};

// ---------------- DSMEM / sync helpers ----------------
__device__ __forceinline__ uint32_t smem_addr_u32(const void* p) {
    return (uint32_t)__cvta_generic_to_shared(p);
}
__device__ __forceinline__ uint32_t mapa_u32(uint32_t a, uint32_t rank) {
    uint32_t d;
    asm("mapa.shared::cluster.u32 %0, %1, %2;" : "=r"(d) : "r"(a), "r"(rank));
    return d;
}
__device__ __forceinline__ void st_remote_f32(uint32_t a, float v) {
    asm volatile("st.shared::cluster.f32 [%0], %1;" :: "r"(a), "f"(v) : "memory");
}
__device__ __forceinline__ void st_flag_release(uint32_t a, unsigned v) {
    asm volatile("st.release.cluster.shared::cluster.u32 [%0], %1;" :: "r"(a), "r"(v) : "memory");
}
__device__ __forceinline__ unsigned ld_flag_acquire(uint32_t a) {
    unsigned v;
    asm volatile("ld.acquire.cluster.shared.u32 %0, [%1];" : "=r"(v) : "r"(a) : "memory");
    return v;
}
__device__ __forceinline__ void fence_cluster_acqrel() {
    asm volatile("fence.acq_rel.cluster;" ::: "memory");
}
__device__ __forceinline__ void cluster_sync_all() {
    asm volatile("barrier.cluster.arrive.aligned;" ::: "memory");
    asm volatile("barrier.cluster.wait.aligned;" ::: "memory");
}
__device__ __forceinline__ void wait_flag(uint32_t a, unsigned tgt) {
    unsigned it = 0;
    while (ld_flag_acquire(a) < tgt) {
        if (++it > 64u) __nanosleep(32);
    }
}

// ---------------- math ----------------
typedef unsigned long long u64;

#define FMA2(d, a, b, c) \
    asm("fma.rn.f32x2 %0, %1, %2, %3;" : "=l"(d) : "l"(a), "l"(b), "l"(c))

__device__ __forceinline__ float hsum2(u64 a) {
    unsigned lo, hi;
    asm("mov.b64 {%0, %1}, %2;" : "=r"(lo), "=r"(hi) : "l"(a));
    return __uint_as_float(lo) + __uint_as_float(hi);
}

__device__ __forceinline__ float cfc_h(float a1, float a2, float aa, float ab) {
    float ff1 = tanhf(a1);
    float ff2 = tanhf(a2);
    float ti  = 0.5f * tanhf(0.5f * (aa + ab)) + 0.5f;   // sigmoid(aa+ab)
    return ff1 + ti * (ff2 - ff1);
}

// one output row: 4 batch rows, k-packed f32x2 accumulation
template<int KP>
__device__ __forceinline__ void mv4(const float* __restrict__ w,
                                    const float* __restrict__ z,
                                    float bias, float* __restrict__ accout, int H) {
    u64 a0 = 0, a1 = 0, a2 = 0, a3 = 0;
    #pragma unroll
    for (int k = 0; k < KP; k += 4) {
        ulonglong2 wv = *reinterpret_cast<const ulonglong2*>(w + k);
        ulonglong2 z0 = *reinterpret_cast<const ulonglong2*>(z + 0 * KP + k);
        ulonglong2 z1 = *reinterpret_cast<const ulonglong2*>(z + 1 * KP + k);
        ulonglong2 z2 = *reinterpret_cast<const ulonglong2*>(z + 2 * KP + k);
        ulonglong2 z3 = *reinterpret_cast<const ulonglong2*>(z + 3 * KP + k);
        FMA2(a0, wv.x, z0.x, a0); FMA2(a0, wv.y, z0.y, a0);
        FMA2(a1, wv.x, z1.x, a1); FMA2(a1, wv.y, z1.y, a1);
        FMA2(a2, wv.x, z2.x, a2); FMA2(a2, wv.y, z2.y, a2);
        FMA2(a3, wv.x, z3.x, a3); FMA2(a3, wv.y, z3.y, a3);
    }
    accout[0 * H] = hsum2(a0) + bias;
    accout[1 * H] = hsum2(a1) + bias;
    accout[2 * H] = hsum2(a2) + bias;
    accout[3 * H] = hsum2(a3) + bias;
}

// ---------------- premask weights into SMEM ----------------
template<int HLOC, int K, int KP>
__device__ void load_weights(float* sW, float* sB, const Params& p, int l, int rowoff, int tid) {
    const float* Ws[4] = { p.W1[l], p.W2[l], p.Wa[l], p.Wb[l] };
    const float* Bs[4] = { p.b1[l], p.b2[l], p.ba[l], p.bb[l] };
    const float* M = p.m[l];
    for (int mat = 0; mat < 4; ++mat) {
        const float* W = Ws[mat];
        for (int idx = tid; idx < HLOC * KP; idx += NT) {
            int j = idx / KP;
            int k = idx - j * KP;
            float v = 0.0f;
            if (k < K) {
                int gi = (rowoff + j) * K + k;
                v = W[gi] * M[gi];
            }
            sW[mat * HLOC * KP + idx] = v;
        }
        for (int j = tid; j < HLOC; j += NT)
            sB[mat * HLOC + j] = Bs[mat][rowoff + j];
    }
}

// ---------------- stage 0: layer 0 ----------------
__device__ void run_stage0(const Params& p, int g, float* smf, uint32_t smu, int tid) {
    float* sW   = smf + STAGE_F;
    float* sB   = sW + 4 * H0 * KP0;
    float* sZ   = sB + 4 * H0;
    float* sAcc = sZ + 4 * KP0;

    load_weights<H0, K0, KP0>(sW, sB, p, 0, 0, tid);
    for (int idx = tid; idx < 4 * KP0; idx += NT) sZ[idx] = 0.f;
    __syncthreads();
    for (int idx = tid; idx < 4 * H0; idx += NT) {
        int r = idx / H0, j = idx - r * H0;
        sZ[r * KP0 + NF + j] = p.h0[(size_t)(g * 4 + r) * 256 + j];
    }
    __syncthreads();
    cluster_sync_all();

    const int xr = tid >> 6, xi = tid & 63;
    const float* xb = p.x + (size_t)(g * 4 + xr) * NTIME * NF + xi;
    float xv = xb[0];

    const uint32_t fl_c01  = smu + FLAG_BYTE(0);            // local: rank1 consumed
    const uint32_t r1_ring = mapa_u32(smu + RING_BYTE, 1);  // rank1's ring01
    const uint32_t r1_F0   = mapa_u32(smu + FLAG_BYTE(0), 1);

    const int is_extra = (tid % 5 == 0) && (tid / 5 < 52);
    const int eidx = 256 + tid / 5;

    for (int t = 0; t < NTIME; ++t) {
        if (tid == 0 && t >= DEPTH) wait_flag(fl_c01, (unsigned)(t + 1 - DEPTH));
        __syncthreads();
        sZ[xr * KP0 + xi] = xv;
        if (t + 1 < NTIME) xv = xb[(size_t)(t + 1) * NF];
        __syncthreads();
        {
            int m = tid / H0, j = tid - m * H0;
            mv4<KP0>(sW + tid * KP0, sZ, sB[tid], sAcc + (m * 4) * H0 + j, H0);
            if (is_extra) {
                int m2 = eidx / H0, j2 = eidx - m2 * H0;
                mv4<KP0>(sW + eidx * KP0, sZ, sB[eidx], sAcc + (m2 * 4) * H0 + j2, H0);
            }
        }
        __syncthreads();
        {
            uint32_t slot = r1_ring + (uint32_t)((t & (DEPTH - 1)) * 320 * 4);
            int r = tid / H0, j = tid - r * H0;
            float h = cfc_h(sAcc[(0 + r) * H0 + j], sAcc[(4 + r) * H0 + j],
                            sAcc[(8 + r) * H0 + j], sAcc[(12 + r) * H0 + j]);
            sZ[r * KP0 + NF + j] = h;
            st_remote_f32(slot + (uint32_t)((r * 80 + j) * 4), h);
            if (is_extra) {
                int r2 = eidx / H0, j2 = eidx - r2 * H0;
                float h2 = cfc_h(sAcc[(0 + r2) * H0 + j2], sAcc[(4 + r2) * H0 + j2],
                                 sAcc[(8 + r2) * H0 + j2], sAcc[(12 + r2) * H0 + j2]);
                sZ[r2 * KP0 + NF + j2] = h2;
                st_remote_f32(slot + (uint32_t)((r2 * 80 + j2) * 4), h2);
            }
        }
        __syncthreads();
        if (tid == 0) { fence_cluster_acqrel(); st_flag_release(r1_F0, (unsigned)(t + 1)); }
    }
    if (p.out_size >= NB * NTIME * 128 + NB * 256) {
        float* hx = p.out + (size_t)NB * NTIME * 128;
        for (int idx = tid; idx < 4 * H0; idx += NT) {
            int r = idx / H0, j = idx - r * H0;
            hx[(size_t)(g * 4 + r) * 256 + j] = sZ[r * KP0 + NF + j];
        }
    }
}

// ---------------- stage 1: layer 1 ----------------
__device__ void run_stage1(const Params& p, int g, float* smf, uint32_t smu, int tid) {
    float* sW   = smf + STAGE_F;
    float* sB   = sW + 4 * H1 * KP1;
    float* sZ   = sB + 4 * H1;
    float* sAcc = sZ + 4 * KP1;
    float* ring01 = smf + 128;   // local ring (float idx of byte 512)

    load_weights<H1, K1, KP1>(sW, sB, p, 1, 0, tid);
    for (int idx = tid; idx < 4 * KP1; idx += NT) sZ[idx] = 0.f;
    __syncthreads();
    for (int idx = tid; idx < 4 * H1; idx += NT) {
        int r = idx / H1, j = idx - r * H1;
        sZ[r * KP1 + H0 + j] = p.h0[(size_t)(g * 4 + r) * 256 + H0 + j];
    }
    __syncthreads();
    cluster_sync_all();

    const uint32_t fl_p0  = smu + FLAG_BYTE(0);   // rank0 produced
    const uint32_t fl_c2a = smu + FLAG_BYTE(1);   // rank2 consumed
    const uint32_t fl_c2b = smu + FLAG_BYTE(2);   // rank3 consumed
    const uint32_t r0_F0  = mapa_u32(smu + FLAG_BYTE(0), 0);
    const uint32_t r2_ring = mapa_u32(smu + RING_BYTE, 2);
    const uint32_t r3_ring = mapa_u32(smu + RING_BYTE, 3);
    const uint32_t r2_F0  = mapa_u32(smu + FLAG_BYTE(0), 2);
    const uint32_t r3_F0  = mapa_u32(smu + FLAG_BYTE(0), 3);

    const int is_extra = (tid % 5 == 0) && (tid / 5 < 52);
    const int eidx = 256 + tid / 5;

    for (int t = 0; t < NTIME; ++t) {
        if (tid == 0)                       wait_flag(fl_p0,  (unsigned)(t + 1));
        else if (tid == 32 && t >= DEPTH)   wait_flag(fl_c2a, (unsigned)(t + 1 - DEPTH));
        else if (tid == 64 && t >= DEPTH)   wait_flag(fl_c2b, (unsigned)(t + 1 - DEPTH));
        __syncthreads();
        {
            const float* islot = ring01 + (t & (DEPTH - 1)) * 320;
            int r = tid / H0, j = tid - r * H0;
            sZ[r * KP1 + j] = islot[r * 80 + j];
            if (is_extra) {
                int r2 = eidx / H0, j2 = eidx - r2 * H0;
                sZ[r2 * KP1 + j2] = islot[r2 * 80 + j2];
            }
        }
        __syncthreads();
        if (tid == 0) st_flag_release(r0_F0, (unsigned)(t + 1));
        if (tid < 4 * H1) {
            int m = tid / H1, j = tid - m * H1;
            mv4<KP1>(sW + tid * KP1, sZ, sB[tid], sAcc + (m * 4) * H1 + j, H1);
        }
        __syncthreads();
        if (tid < 4 * H1) {
            uint32_t so = (uint32_t)(((t & (DEPTH - 1)) * 224) * 4);
            int r = tid / H1, j = tid - r * H1;
            float h = cfc_h(sAcc[(0 + r) * H1 + j], sAcc[(4 + r) * H1 + j],
                            sAcc[(8 + r) * H1 + j], sAcc[(12 + r) * H1 + j]);
            sZ[r * KP1 + H0 + j] = h;
            uint32_t off = so + (uint32_t)((r * 56 + j) * 4);
            st_remote_f32(r2_ring + off, h);
            st_remote_f32(r3_ring + off, h);
        }
        __syncthreads();
        if (tid == 0) {
            fence_cluster_acqrel();
            st_flag_release(r2_F0, (unsigned)(t + 1));
            st_flag_release(r3_F0, (unsigned)(t + 1));
        }
    }
    if (p.out_size >= NB * NTIME * 128 + NB * 256) {
        float* hx = p.out + (size_t)NB * NTIME * 128;
        for (int idx = tid; idx < 4 * H1; idx += NT) {
            int r = idx / H1, j = idx - r * H1;
            hx[(size_t)(g * 4 + r) * 256 + H0 + j] = sZ[r * KP1 + H0 + j];
        }
    }
}

// ---------------- stage 2: layer 2 half ----------------
template<int HALF>
__device__ void run_stage2(const Params& p, int g, float* smf, uint32_t smu, int tid) {
    float* sW   = smf + STAGE_F;
    float* sB   = sW + 4 * H2H * KP2;
    float* sZ   = sB + 4 * H2H;
    float* sAcc = sZ + 4 * KP2;
    float* ring12   = smf + 128;                    // byte 512
    float* ringPeer = smf + 128 + DEPTH * 224;      // byte 7680

    const int IN = H1;                       // 51
    const int zoff  = IN + HALF * 64;
    const int zpeer = IN + (1 - HALF) * 64;
    const int peer_rank = HALF ? 2 : 3;

    load_weights<H2H, K2, KP2>(sW, sB, p, 2, HALF * 64, tid);
    for (int idx = tid; idx < 4 * KP2; idx += NT) sZ[idx] = 0.f;
    __syncthreads();
    for (int idx = tid; idx < 4 * H2; idx += NT) {
        int r = idx >> 7, u = idx & 127;
        sZ[r * KP2 + IN + u] = p.h0[(size_t)(g * 4 + r) * 256 + 128 + u];
    }
    __syncthreads();
    cluster_sync_all();

    const uint32_t fl_p1 = smu + FLAG_BYTE(0);   // rank1 produced
    const uint32_t fl_pp = smu + FLAG_BYTE(1);   // peer produced into my ringPeer
    const uint32_t fl_pc = smu + FLAG_BYTE(2);   // peer consumed my pushes
    const uint32_t r1_Fc = mapa_u32(smu + FLAG_BYTE(1 + HALF), 1);  // rank1 F1(half0)/F2(half1)
    const uint32_t pr_F1 = mapa_u32(smu + FLAG_BYTE(1), (uint32_t)peer_rank);
    const uint32_t pr_F2 = mapa_u32(smu + FLAG_BYTE(2), (uint32_t)peer_rank);
    const uint32_t pr_ringP = mapa_u32(smu + RINGP_BYTE, (uint32_t)peer_rank);

    const int r2 = tid >> 6, j2 = tid & 63;
    const int cr = tid / IN, cj = tid - cr * IN;     // copy mapping (204 items)

    for (int t = 0; t < NTIME; ++t) {
        if (tid == 0)                     wait_flag(fl_p1, (unsigned)(t + 1));
        else if (tid == 32 && t >= 1)     wait_flag(fl_pp, (unsigned)t);
        else if (tid == 64 && t >= DEPTH) wait_flag(fl_pc, (unsigned)(t + 1 - DEPTH));
        __syncthreads();
        {
            const float* islot = ring12 + (t & (DEPTH - 1)) * 224;
            if (tid < 4 * IN) sZ[cr * KP2 + cj] = islot[cr * 56 + cj];
            if (t >= 1) {
                const float* ps = ringPeer + ((t - 1) & (DEPTH - 1)) * 256;
                sZ[r2 * KP2 + zpeer + j2] = ps[r2 * 64 + j2];
            }
        }
        __syncthreads();
        if (tid == 0) {
            st_flag_release(r1_Fc, (unsigned)(t + 1));
            if (t >= 1) st_flag_release(pr_F2, (unsigned)t);
        }
        {
            int m = tid >> 6, j = tid & 63;
            mv4<KP2>(sW + tid * KP2, sZ, sB[tid], sAcc + (m * 4) * H2H + j, H2H);
        }
        __syncthreads();
        {
            float h = cfc_h(sAcc[(0 + r2) * H2H + j2], sAcc[(4 + r2) * H2H + j2],
                            sAcc[(8 + r2) * H2H + j2], sAcc[(12 + r2) * H2H + j2]);
            sZ[r2 * KP2 + zoff + j2] = h;
            st_remote_f32(pr_ringP + (uint32_t)((((t & (DEPTH - 1)) * 256) + r2 * 64 + j2) * 4), h);
            p.out[((size_t)(g * 4 + r2) * NTIME + t) * 128 + HALF * 64 + j2] = h;
        }
        __syncthreads();
        if (tid == 0) { fence_cluster_acqrel(); st_flag_release(pr_F1, (unsigned)(t + 1)); }
    }
    if (p.out_size >= NB * NTIME * 128 + NB * 256) {
        float* hx = p.out + (size_t)NB * NTIME * 128;
        hx[(size_t)(g * 4 + r2) * 256 + 128 + HALF * 64 + j2] = sZ[r2 * KP2 + zoff + j2];
    }
}

// ---------------- kernel ----------------
__global__ void __launch_bounds__(NT, 1) cfc_kernel(Params p) {
    extern __shared__ unsigned char smraw[];
    float* smf = (float*)smraw;
    const uint32_t smu = smem_addr_u32(smraw);
    const int stage = blockIdx.x & 3;
    const int g     = blockIdx.x >> 2;
    const int tid   = threadIdx.x;

    // init local flags (fresh every launch / graph replay)
    if (tid < 16) *(unsigned*)(smraw + FLAG_BYTE(tid)) = 0u;

    if      (stage == 0) run_stage0(p, g, smf, smu, tid);
    else if (stage == 1) run_stage1(p, g, smf, smu, tid);
    else if (stage == 2) run_stage2<0>(p, g, smf, smu, tid);
    else                 run_stage2<1>(p, g, smf, smu, tid);

    cluster_sync_all();   // no CTA exits while peers may still push into its smem
}

// ---------------- host launch ----------------
extern "C" void kernel_launch(void* const* d_in, const int* in_sizes, int n_in,
                              void* d_out, int out_size) {
    Params p;
    p.x  = (const float*)d_in[0];
    p.h0 = (const float*)d_in[1];
    bool sig_order = (n_in > 4 && in_sizes[4] == 77);
    for (int l = 0; l < 3; ++l) {
        int b = 2 + 9 * l;
        p.m[l] = (const float*)d_in[b];
        if (!sig_order) {
            p.W1[l] = (const float*)d_in[b + 1];
            p.W2[l] = (const float*)d_in[b + 2];
            p.Wa[l] = (const float*)d_in[b + 3];
            p.Wb[l] = (const float*)d_in[b + 4];
            p.b1[l] = (const float*)d_in[b + 5];
            p.b2[l] = (const float*)d_in[b + 6];
            p.ba[l] = (const float*)d_in[b + 7];
            p.bb[l] = (const float*)d_in[b + 8];
        } else {
            p.W1[l] = (const float*)d_in[b + 1];
            p.b1[l] = (const float*)d_in[b + 2];
            p.W2[l] = (const float*)d_in[b + 3];
            p.b2[l] = (const float*)d_in[b + 4];
            p.Wa[l] = (const float*)d_in[b + 5];
            p.ba[l] = (const float*)d_in[b + 6];
            p.Wb[l] = (const float*)d_in[b + 7];
            p.bb[l] = (const float*)d_in[b + 8];
        }
    }
    p.out = (float*)d_out;
    p.out_size = out_size;

    cudaFuncSetAttribute(cfc_kernel, cudaFuncAttributeMaxDynamicSharedMemorySize, SMEM_BYTES);

    cudaLaunchConfig_t cfg = {};
    cfg.gridDim  = dim3(4 * NG, 1, 1);
    cfg.blockDim = dim3(NT, 1, 1);
    cfg.dynamicSmemBytes = SMEM_BYTES;
    cfg.stream = 0;
    cudaLaunchAttribute attr[1];
    attr[0].id = cudaLaunchAttributeClusterDimension;
    attr[0].val.clusterDim.x = 4;
    attr[0].val.clusterDim.y = 1;
    attr[0].val.clusterDim.z = 1;
    cfg.attrs = attr;
    cfg.numAttrs = 1;
    cudaLaunchKernelEx(&cfg, cfc_kernel, p);
}

// round 7
// speedup vs baseline: 1.0593x; 1.0007x over previous
#include <cuda_runtime.h>
#include <stdint.h>
#include <stddef.h>

// ---------------- problem constants ----------------
#define NT      256
#define NG      32
#define DEPTH   8
#define NB      128
#define NTIME   4096
#define NF      64

#define H0 77
#define K0 141
#define KP0 148
#define H1 51
#define K1 128
#define KP1 132
#define H2 128
#define K2 179
#define KP2 180
#define H2H 64

// ---- shared memory layout (bytes) ----
// [0,512)    : flags (flag i at byte i*32, as u32)
// [512,15872): ring region
//    rank1: ring01  = DEPTH slots * 320 floats   (slot s at 512 + s*320*4)
//    rank2/3: ring12 = DEPTH * 224 floats at 512; ringPeer = DEPTH * 256 floats at 7680
// [15872, ..): stage area (weights, biases, z, acc) max 48080 floats
#define FLAG_BYTE(i)   ((i) * 32)
#define RING_BYTE      512
#define RINGP_BYTE     (512 + DEPTH * 224 * 4)     // 7680
#define STAGE_F        3968                         // float index of stage area
#define STAGE_MAXF     48080
#define SMEM_BYTES     (15872 + STAGE_MAXF * 4)     // 208192

struct Params {
    const float* x;
    const float* h0;
    const float* m[3];
    const float* W1[3]; const float* W2[3]; const float* Wa[3]; const float* Wb[3];
    const float* b1[3]; const float* b2[3]; const float* ba[3]; const float* bb[3];
    float* out;
    int out_size;
};

// ---------------- DSMEM / sync helpers ----------------
__device__ __forceinline__ uint32_t smem_addr_u32(const void* p) {
    return (uint32_t)__cvta_generic_to_shared(p);
}
__device__ __forceinline__ uint32_t mapa_u32(uint32_t a, uint32_t rank) {
    uint32_t d;
    asm("mapa.shared::cluster.u32 %0, %1, %2;" : "=r"(d) : "r"(a), "r"(rank));
    return d;
}
__device__ __forceinline__ void st_remote_f32(uint32_t a, float v) {
    asm volatile("st.shared::cluster.f32 [%0], %1;" :: "r"(a), "f"(v) : "memory");
}
__device__ __forceinline__ void st_flag_release(uint32_t a, unsigned v) {
    asm volatile("st.release.cluster.shared::cluster.u32 [%0], %1;" :: "r"(a), "r"(v) : "memory");
}
__device__ __forceinline__ unsigned ld_flag_acquire(uint32_t a) {
    unsigned v;
    asm volatile("ld.acquire.cluster.shared.u32 %0, [%1];" : "=r"(v) : "r"(a) : "memory");
    return v;
}
__device__ __forceinline__ void fence_cluster_acqrel() {
    asm volatile("fence.acq_rel.cluster;" ::: "memory");
}
__device__ __forceinline__ void cluster_sync_all() {
    asm volatile("barrier.cluster.arrive.aligned;" ::: "memory");
    asm volatile("barrier.cluster.wait.aligned;" ::: "memory");
}
__device__ __forceinline__ void wait_flag(uint32_t a, unsigned tgt) {
    unsigned it = 0;
    while (ld_flag_acquire(a) < tgt) {
        if (++it > 64u) __nanosleep(32);
    }
}

// ---------------- math ----------------
typedef unsigned long long u64;

#define FMA2(d, a, b, c) \
    asm("fma.rn.f32x2 %0, %1, %2, %3;" : "=l"(d) : "l"(a), "l"(b), "l"(c))

__device__ __forceinline__ float hsum2(u64 a) {
    unsigned lo, hi;
    asm("mov.b64 {%0, %1}, %2;" : "=r"(lo), "=r"(hi) : "l"(a));
    return __uint_as_float(lo) + __uint_as_float(hi);
}

__device__ __forceinline__ float cfc_h(float a1, float a2, float aa, float ab) {
    float ff1 = tanhf(a1);
    float ff2 = tanhf(a2);
    float ti  = 0.5f * tanhf(0.5f * (aa + ab)) + 0.5f;   // sigmoid(aa+ab)
    return ff1 + ti * (ff2 - ff1);
}

// one output row: 4 batch rows, k-packed f32x2 accumulation
template<int KP>
__device__ __forceinline__ void mv4(const float* __restrict__ w,
                                    const float* __restrict__ z,
                                    float bias, float* __restrict__ accout, int H) {
    u64 a0 = 0, a1 = 0, a2 = 0, a3 = 0;
    #pragma unroll
    for (int k = 0; k < KP; k += 4) {
        ulonglong2 wv = *reinterpret_cast<const ulonglong2*>(w + k);
        ulonglong2 z0 = *reinterpret_cast<const ulonglong2*>(z + 0 * KP + k);
        ulonglong2 z1 = *reinterpret_cast<const ulonglong2*>(z + 1 * KP + k);
        ulonglong2 z2 = *reinterpret_cast<const ulonglong2*>(z + 2 * KP + k);
        ulonglong2 z3 = *reinterpret_cast<const ulonglong2*>(z + 3 * KP + k);
        FMA2(a0, wv.x, z0.x, a0); FMA2(a0, wv.y, z0.y, a0);
        FMA2(a1, wv.x, z1.x, a1); FMA2(a1, wv.y, z1.y, a1);
        FMA2(a2, wv.x, z2.x, a2); FMA2(a2, wv.y, z2.y, a2);
        FMA2(a3, wv.x, z3.x, a3); FMA2(a3, wv.y, z3.y, a3);
    }
    accout[0 * H] = hsum2(a0) + bias;
    accout[1 * H] = hsum2(a1) + bias;
    accout[2 * H] = hsum2(a2) + bias;
    accout[3 * H] = hsum2(a3) + bias;
}

// ---------------- premask weights into SMEM ----------------
template<int HLOC, int K, int KP>
__device__ void load_weights(float* sW, float* sB, const Params& p, int l, int rowoff, int tid) {
    const float* Ws[4] = { p.W1[l], p.W2[l], p.Wa[l], p.Wb[l] };
    const float* Bs[4] = { p.b1[l], p.b2[l], p.ba[l], p.bb[l] };
    const float* M = p.m[l];
    for (int mat = 0; mat < 4; ++mat) {
        const float* W = Ws[mat];
        for (int idx = tid; idx < HLOC * KP; idx += NT) {
            int j = idx / KP;
            int k = idx - j * KP;
            float v = 0.0f;
            if (k < K) {
                int gi = (rowoff + j) * K + k;
                v = W[gi] * M[gi];
            }
            sW[mat * HLOC * KP + idx] = v;
        }
        for (int j = tid; j < HLOC; j += NT)
            sB[mat * HLOC + j] = Bs[mat][rowoff + j];
    }
}

// ---------------- stage 0: layer 0 ----------------
__device__ void run_stage0(const Params& p, int g, float* smf, uint32_t smu, int tid) {
    float* sW   = smf + STAGE_F;
    float* sB   = sW + 4 * H0 * KP0;
    float* sZ   = sB + 4 * H0;
    float* sAcc = sZ + 4 * KP0;

    load_weights<H0, K0, KP0>(sW, sB, p, 0, 0, tid);
    for (int idx = tid; idx < 4 * KP0; idx += NT) sZ[idx] = 0.f;
    __syncthreads();
    for (int idx = tid; idx < 4 * H0; idx += NT) {
        int r = idx / H0, j = idx - r * H0;
        sZ[r * KP0 + NF + j] = p.h0[(size_t)(g * 4 + r) * 256 + j];
    }
    __syncthreads();
    cluster_sync_all();

    const int xr = tid >> 6, xi = tid & 63;
    const float* xb = p.x + (size_t)(g * 4 + xr) * NTIME * NF + xi;
    float xv = xb[0];

    const uint32_t fl_c01  = smu + FLAG_BYTE(0);            // local: rank1 consumed
    const uint32_t r1_ring = mapa_u32(smu + RING_BYTE, 1);  // rank1's ring01
    const uint32_t r1_F0   = mapa_u32(smu + FLAG_BYTE(0), 1);

    const int is_extra = (tid % 5 == 0) && (tid / 5 < 52);
    const int eidx = 256 + tid / 5;

    for (int t = 0; t < NTIME; ++t) {
        if (tid == 0 && t >= DEPTH) wait_flag(fl_c01, (unsigned)(t + 1 - DEPTH));
        __syncthreads();
        sZ[xr * KP0 + xi] = xv;
        if (t + 1 < NTIME) xv = xb[(size_t)(t + 1) * NF];
        __syncthreads();
        {
            int m = tid / H0, j = tid - m * H0;
            mv4<KP0>(sW + tid * KP0, sZ, sB[tid], sAcc + (m * 4) * H0 + j, H0);
            if (is_extra) {
                int m2 = eidx / H0, j2 = eidx - m2 * H0;
                mv4<KP0>(sW + eidx * KP0, sZ, sB[eidx], sAcc + (m2 * 4) * H0 + j2, H0);
            }
        }
        __syncthreads();
        {
            uint32_t slot = r1_ring + (uint32_t)((t & (DEPTH - 1)) * 320 * 4);
            int r = tid / H0, j = tid - r * H0;
            float h = cfc_h(sAcc[(0 + r) * H0 + j], sAcc[(4 + r) * H0 + j],
                            sAcc[(8 + r) * H0 + j], sAcc[(12 + r) * H0 + j]);
            sZ[r * KP0 + NF + j] = h;
            st_remote_f32(slot + (uint32_t)((r * 80 + j) * 4), h);
            if (is_extra) {
                int r2 = eidx / H0, j2 = eidx - r2 * H0;
                float h2 = cfc_h(sAcc[(0 + r2) * H0 + j2], sAcc[(4 + r2) * H0 + j2],
                                 sAcc[(8 + r2) * H0 + j2], sAcc[(12 + r2) * H0 + j2]);
                sZ[r2 * KP0 + NF + j2] = h2;
                st_remote_f32(slot + (uint32_t)((r2 * 80 + j2) * 4), h2);
            }
        }
        __syncthreads();
        if (tid == 0) { fence_cluster_acqrel(); st_flag_release(r1_F0, (unsigned)(t + 1)); }
    }
    if (p.out_size >= NB * NTIME * 128 + NB * 256) {
        float* hx = p.out + (size_t)NB * NTIME * 128;
        for (int idx = tid; idx < 4 * H0; idx += NT) {
            int r = idx / H0, j = idx - r * H0;
            hx[(size_t)(g * 4 + r) * 256 + j] = sZ[r * KP0 + NF + j];
        }
    }
}

// ---------------- stage 1: layer 1 ----------------
__device__ void run_stage1(const Params& p, int g, float* smf, uint32_t smu, int tid) {
    float* sW   = smf + STAGE_F;
    float* sB   = sW + 4 * H1 * KP1;
    float* sZ   = sB + 4 * H1;
    float* sAcc = sZ + 4 * KP1;
    float* ring01 = smf + 128;   // local ring (float idx of byte 512)

    load_weights<H1, K1, KP1>(sW, sB, p, 1, 0, tid);
    for (int idx = tid; idx < 4 * KP1; idx += NT) sZ[idx] = 0.f;
    __syncthreads();
    for (int idx = tid; idx < 4 * H1; idx += NT) {
        int r = idx / H1, j = idx - r * H1;
        sZ[r * KP1 + H0 + j] = p.h0[(size_t)(g * 4 + r) * 256 + H0 + j];
    }
    __syncthreads();
    cluster_sync_all();

    const uint32_t fl_p0  = smu + FLAG_BYTE(0);   // rank0 produced
    const uint32_t fl_c2a = smu + FLAG_BYTE(1);   // rank2 consumed
    const uint32_t fl_c2b = smu + FLAG_BYTE(2);   // rank3 consumed
    const uint32_t r0_F0  = mapa_u32(smu + FLAG_BYTE(0), 0);
    const uint32_t r2_ring = mapa_u32(smu + RING_BYTE, 2);
    const uint32_t r3_ring = mapa_u32(smu + RING_BYTE, 3);
    const uint32_t r2_F0  = mapa_u32(smu + FLAG_BYTE(0), 2);
    const uint32_t r3_F0  = mapa_u32(smu + FLAG_BYTE(0), 3);

    const int is_extra = (tid % 5 == 0) && (tid / 5 < 52);
    const int eidx = 256 + tid / 5;

    for (int t = 0; t < NTIME; ++t) {
        if (tid == 0)                       wait_flag(fl_p0,  (unsigned)(t + 1));
        else if (tid == 32 && t >= DEPTH)   wait_flag(fl_c2a, (unsigned)(t + 1 - DEPTH));
        else if (tid == 64 && t >= DEPTH)   wait_flag(fl_c2b, (unsigned)(t + 1 - DEPTH));
        __syncthreads();
        {
            const float* islot = ring01 + (t & (DEPTH - 1)) * 320;
            int r = tid / H0, j = tid - r * H0;
            sZ[r * KP1 + j] = islot[r * 80 + j];
            if (is_extra) {
                int r2 = eidx / H0, j2 = eidx - r2 * H0;
                sZ[r2 * KP1 + j2] = islot[r2 * 80 + j2];
            }
        }
        __syncthreads();
        if (tid == 0) st_flag_release(r0_F0, (unsigned)(t + 1));
        if (tid < 4 * H1) {
            int m = tid / H1, j = tid - m * H1;
            mv4<KP1>(sW + tid * KP1, sZ, sB[tid], sAcc + (m * 4) * H1 + j, H1);
        }
        __syncthreads();
        if (tid < 4 * H1) {
            uint32_t so = (uint32_t)(((t & (DEPTH - 1)) * 224) * 4);
            int r = tid / H1, j = tid - r * H1;
            float h = cfc_h(sAcc[(0 + r) * H1 + j], sAcc[(4 + r) * H1 + j],
                            sAcc[(8 + r) * H1 + j], sAcc[(12 + r) * H1 + j]);
            sZ[r * KP1 + H0 + j] = h;
            uint32_t off = so + (uint32_t)((r * 56 + j) * 4);
            st_remote_f32(r2_ring + off, h);
            st_remote_f32(r3_ring + off, h);
        }
        __syncthreads();
        if (tid == 0) {
            fence_cluster_acqrel();
            st_flag_release(r2_F0, (unsigned)(t + 1));
            st_flag_release(r3_F0, (unsigned)(t + 1));
        }
    }
    if (p.out_size >= NB * NTIME * 128 + NB * 256) {
        float* hx = p.out + (size_t)NB * NTIME * 128;
        for (int idx = tid; idx < 4 * H1; idx += NT) {
            int r = idx / H1, j = idx - r * H1;
            hx[(size_t)(g * 4 + r) * 256 + H0 + j] = sZ[r * KP1 + H0 + j];
        }
    }
}

// ---------------- stage 2: layer 2 half ----------------
template<int HALF>
__device__ void run_stage2(const Params& p, int g, float* smf, uint32_t smu, int tid) {
    float* sW   = smf + STAGE_F;
    float* sB   = sW + 4 * H2H * KP2;
    float* sZ   = sB + 4 * H2H;
    float* sAcc = sZ + 4 * KP2;
    float* ring12   = smf + 128;                    // byte 512
    float* ringPeer = smf + 128 + DEPTH * 224;      // byte 7680

    const int IN = H1;                       // 51
    const int zoff  = IN + HALF * 64;
    const int zpeer = IN + (1 - HALF) * 64;
    const int peer_rank = HALF ? 2 : 3;

    load_weights<H2H, K2, KP2>(sW, sB, p, 2, HALF * 64, tid);
    for (int idx = tid; idx < 4 * KP2; idx += NT) sZ[idx] = 0.f;
    __syncthreads();
    for (int idx = tid; idx < 4 * H2; idx += NT) {
        int r = idx >> 7, u = idx & 127;
        sZ[r * KP2 + IN + u] = p.h0[(size_t)(g * 4 + r) * 256 + 128 + u];
    }
    __syncthreads();
    cluster_sync_all();

    const uint32_t fl_p1 = smu + FLAG_BYTE(0);   // rank1 produced
    const uint32_t fl_pp = smu + FLAG_BYTE(1);   // peer produced into my ringPeer
    const uint32_t fl_pc = smu + FLAG_BYTE(2);   // peer consumed my pushes
    const uint32_t r1_Fc = mapa_u32(smu + FLAG_BYTE(1 + HALF), 1);  // rank1 F1(half0)/F2(half1)
    const uint32_t pr_F1 = mapa_u32(smu + FLAG_BYTE(1), (uint32_t)peer_rank);
    const uint32_t pr_F2 = mapa_u32(smu + FLAG_BYTE(2), (uint32_t)peer_rank);
    const uint32_t pr_ringP = mapa_u32(smu + RINGP_BYTE, (uint32_t)peer_rank);

    const int r2 = tid >> 6, j2 = tid & 63;
    const int cr = tid / IN, cj = tid - cr * IN;     // copy mapping (204 items)

    for (int t = 0; t < NTIME; ++t) {
        if (tid == 0)                     wait_flag(fl_p1, (unsigned)(t + 1));
        else if (tid == 32 && t >= 1)     wait_flag(fl_pp, (unsigned)t);
        else if (tid == 64 && t >= DEPTH) wait_flag(fl_pc, (unsigned)(t + 1 - DEPTH));
        __syncthreads();
        {
            const float* islot = ring12 + (t & (DEPTH - 1)) * 224;
            if (tid < 4 * IN) sZ[cr * KP2 + cj] = islot[cr * 56 + cj];
            if (t >= 1) {
                const float* ps = ringPeer + ((t - 1) & (DEPTH - 1)) * 256;
                sZ[r2 * KP2 + zpeer + j2] = ps[r2 * 64 + j2];
            }
        }
        __syncthreads();
        if (tid == 0) {
            st_flag_release(r1_Fc, (unsigned)(t + 1));
            if (t >= 1) st_flag_release(pr_F2, (unsigned)t);
        }
        {
            int m = tid >> 6, j = tid & 63;
            mv4<KP2>(sW + tid * KP2, sZ, sB[tid], sAcc + (m * 4) * H2H + j, H2H);
        }
        __syncthreads();
        {
            float h = cfc_h(sAcc[(0 + r2) * H2H + j2], sAcc[(4 + r2) * H2H + j2],
                            sAcc[(8 + r2) * H2H + j2], sAcc[(12 + r2) * H2H + j2]);
            sZ[r2 * KP2 + zoff + j2] = h;
            st_remote_f32(pr_ringP + (uint32_t)((((t & (DEPTH - 1)) * 256) + r2 * 64 + j2) * 4), h);
            p.out[((size_t)(g * 4 + r2) * NTIME + t) * 128 + HALF * 64 + j2] = h;
        }
        __syncthreads();
        if (tid == 0) { fence_cluster_acqrel(); st_flag_release(pr_F1, (unsigned)(t + 1)); }
    }
    if (p.out_size >= NB * NTIME * 128 + NB * 256) {
        float* hx = p.out + (size_t)NB * NTIME * 128;
        hx[(size_t)(g * 4 + r2) * 256 + 128 + HALF * 64 + j2] = sZ[r2 * KP2 + zoff + j2];
    }
}

// ---------------- kernel ----------------
__global__ void __launch_bounds__(NT, 1) cfc_kernel(Params p) {
    extern __shared__ unsigned char smraw[];
    float* smf = (float*)smraw;
    const uint32_t smu = smem_addr_u32(smraw);
    const int stage = blockIdx.x & 3;
    const int g     = blockIdx.x >> 2;
    const int tid   = threadIdx.x;

    // init local flags (fresh every launch / graph replay)
    if (tid < 16) *(unsigned*)(smraw + FLAG_BYTE(tid)) = 0u;

    if      (stage == 0) run_stage0(p, g, smf, smu, tid);
    else if (stage == 1) run_stage1(p, g, smf, smu, tid);
    else if (stage == 2) run_stage2<0>(p, g, smf, smu, tid);
    else                 run_stage2<1>(p, g, smf, smu, tid);

    cluster_sync_all();   // no CTA exits while peers may still push into its smem
}

// ---------------- host launch ----------------
extern "C" void kernel_launch(void* const* d_in, const int* in_sizes, int n_in,
                              void* d_out, int out_size) {
    Params p;
    p.x  = (const float*)d_in[0];
    p.h0 = (const float*)d_in[1];
    bool sig_order = (n_in > 4 && in_sizes[4] == 77);
    for (int l = 0; l < 3; ++l) {
        int b = 2 + 9 * l;
        p.m[l] = (const float*)d_in[b];
        if (!sig_order) {
            p.W1[l] = (const float*)d_in[b + 1];
            p.W2[l] = (const float*)d_in[b + 2];
            p.Wa[l] = (const float*)d_in[b + 3];
            p.Wb[l] = (const float*)d_in[b + 4];
            p.b1[l] = (const float*)d_in[b + 5];
            p.b2[l] = (const float*)d_in[b + 6];
            p.ba[l] = (const float*)d_in[b + 7];
            p.bb[l] = (const float*)d_in[b + 8];
        } else {
            p.W1[l] = (const float*)d_in[b + 1];
            p.b1[l] = (const float*)d_in[b + 2];
            p.W2[l] = (const float*)d_in[b + 3];
            p.b2[l] = (const float*)d_in[b + 4];
            p.Wa[l] = (const float*)d_in[b + 5];
            p.ba[l] = (const float*)d_in[b + 6];
            p.Wb[l] = (const float*)d_in[b + 7];
            p.bb[l] = (const float*)d_in[b + 8];
        }
    }
    p.out = (float*)d_out;
    p.out_size = out_size;

    cudaFuncSetAttribute(cfc_kernel, cudaFuncAttributeMaxDynamicSharedMemorySize, SMEM_BYTES);

    cudaLaunchConfig_t cfg = {};
    cfg.gridDim  = dim3(4 * NG, 1, 1);
    cfg.blockDim = dim3(NT, 1, 1);
    cfg.dynamicSmemBytes = SMEM_BYTES;
    cfg.stream = 0;
    cudaLaunchAttribute attr[1];
    attr[0].id = cudaLaunchAttributeClusterDimension;
    attr[0].val.clusterDim.x = 4;
    attr[0].val.clusterDim.y = 1;
    attr[0].val.clusterDim.z = 1;
    cfg.attrs = attr;
    cfg.numAttrs = 1;
    cudaLaunchKernelEx(&cfg, cfc_kernel, p);
}

// round 8
// speedup vs baseline: 1.4091x; 1.3302x over previous
#include <cuda_runtime.h>
#include <stdint.h>
#include <stddef.h>

// ---------------- problem constants ----------------
#define NT      512
#define NG      32
#define DEPTH   8
#define NB      128
#define NTIME   4096
#define NF      64

#define H0 77
#define K0 141
#define KP0 148
#define KA0 76
#define KB0 72
#define H1 51
#define K1 128
#define KP1 132
#define KA1 68
#define KB1 64
#define H2 128
#define K2 179
#define KP2 180
#define KA2 92
#define KB2 88
#define H2H 64
#define RKC 32            // register-cached k floats per unit

// ---- shared memory layout (bytes) ----
// [0,512)    : flags (flag i at byte i*32)
// [512,15872): rings
//    rank1: ring01 = DEPTH * 320 floats at byte 512
//    rank2/3: ring12 = DEPTH * 224 floats at 512; ringPeer = DEPTH * 256 floats at 7680
// [15872,..) : stage area
#define FLAG_BYTE(i)   ((i) * 32)
#define RING_BYTE      512
#define RINGP_BYTE     (512 + DEPTH * 224 * 4)   // 7680
#define STAGE_F        3968                       // float index of stage area
#define STAGE_MAXF     49152
#define SMEM_BYTES     (15872 + STAGE_MAXF * 4)   // 212480

struct Params {
    const float* x;
    const float* h0;
    const float* m[3];
    const float* W1[3]; const float* W2[3]; const float* Wa[3]; const float* Wb[3];
    const float* b1[3]; const float* b2[3]; const float* ba[3]; const float* bb[3];
    float* out;
    int out_size;
};

// ---------------- DSMEM / sync helpers ----------------
__device__ __forceinline__ uint32_t smem_addr_u32(const void* p) {
    return (uint32_t)__cvta_generic_to_shared(p);
}
__device__ __forceinline__ uint32_t mapa_u32(uint32_t a, uint32_t rank) {
    uint32_t d;
    asm("mapa.shared::cluster.u32 %0, %1, %2;" : "=r"(d) : "r"(a), "r"(rank));
    return d;
}
__device__ __forceinline__ void st_remote_f32(uint32_t a, float v) {
    asm volatile("st.shared::cluster.f32 [%0], %1;" :: "r"(a), "f"(v) : "memory");
}
__device__ __forceinline__ void st_flag_release(uint32_t a, unsigned v) {
    asm volatile("st.release.cluster.shared::cluster.u32 [%0], %1;" :: "r"(a), "r"(v) : "memory");
}
__device__ __forceinline__ unsigned ld_flag_acquire(uint32_t a) {
    unsigned v;
    asm volatile("ld.acquire.cluster.shared.u32 %0, [%1];" : "=r"(v) : "r"(a) : "memory");
    return v;
}
__device__ __forceinline__ void fence_cluster_acqrel() {
    asm volatile("fence.acq_rel.cluster;" ::: "memory");
}
__device__ __forceinline__ void cluster_sync_all() {
    asm volatile("barrier.cluster.arrive.aligned;" ::: "memory");
    asm volatile("barrier.cluster.wait.aligned;" ::: "memory");
}
__device__ __forceinline__ void wait_flag(uint32_t a, unsigned tgt) {
    unsigned it = 0;
    while (ld_flag_acquire(a) < tgt) {
        if (++it > 64u) __nanosleep(32);
    }
}

// ---------------- math ----------------
typedef unsigned long long u64;

#define FMA2(d, a, b, c) \
    asm("fma.rn.f32x2 %0, %1, %2, %3;" : "=l"(d) : "l"(a), "l"(b), "l"(c))

__device__ __forceinline__ float hsum2(u64 a) {
    unsigned lo, hi;
    asm("mov.b64 {%0, %1}, %2;" : "=r"(lo), "=r"(hi) : "l"(a));
    return __uint_as_float(lo) + __uint_as_float(hi);
}

__device__ __forceinline__ float cfc_h(float a1, float a2, float aa, float ab) {
    float ff1 = tanhf(a1);
    float ff2 = tanhf(a2);
    float ti  = 0.5f * tanhf(0.5f * (aa + ab)) + 0.5f;   // sigmoid(aa+ab)
    return ff1 + ti * (ff2 - ff1);
}

// partial matvec over one k-slice: 4 batch rows, k-packed f32x2.
// wsm = weight row + koff + RK ; wreg = cached first RK floats ; zb = sZ + koff
template<int KP, int KLEN, int RK>
__device__ __forceinline__ void mv4r(const float* __restrict__ wsm,
                                     const u64* __restrict__ wreg,
                                     const float* __restrict__ zb,
                                     float* __restrict__ o) {
    u64 a0 = 0, a1 = 0, a2 = 0, a3 = 0;
    if constexpr (RK > 0) {
        #pragma unroll
        for (int c = 0; c < RK / 4; ++c) {
            u64 wx = wreg[2 * c], wy = wreg[2 * c + 1];
            ulonglong2 z0 = *(const ulonglong2*)(zb + 0 * KP + 4 * c);
            ulonglong2 z1 = *(const ulonglong2*)(zb + 1 * KP + 4 * c);
            ulonglong2 z2 = *(const ulonglong2*)(zb + 2 * KP + 4 * c);
            ulonglong2 z3 = *(const ulonglong2*)(zb + 3 * KP + 4 * c);
            FMA2(a0, wx, z0.x, a0); FMA2(a0, wy, z0.y, a0);
            FMA2(a1, wx, z1.x, a1); FMA2(a1, wy, z1.y, a1);
            FMA2(a2, wx, z2.x, a2); FMA2(a2, wy, z2.y, a2);
            FMA2(a3, wx, z3.x, a3); FMA2(a3, wy, z3.y, a3);
        }
    }
    #pragma unroll
    for (int k = 0; k < KLEN - RK; k += 4) {
        ulonglong2 wv = *(const ulonglong2*)(wsm + k);
        ulonglong2 z0 = *(const ulonglong2*)(zb + RK + 0 * KP + k);
        ulonglong2 z1 = *(const ulonglong2*)(zb + RK + 1 * KP + k);
        ulonglong2 z2 = *(const ulonglong2*)(zb + RK + 2 * KP + k);
        ulonglong2 z3 = *(const ulonglong2*)(zb + RK + 3 * KP + k);
        FMA2(a0, wv.x, z0.x, a0); FMA2(a0, wv.y, z0.y, a0);
        FMA2(a1, wv.x, z1.x, a1); FMA2(a1, wv.y, z1.y, a1);
        FMA2(a2, wv.x, z2.x, a2); FMA2(a2, wv.y, z2.y, a2);
        FMA2(a3, wv.x, z3.x, a3); FMA2(a3, wv.y, z3.y, a3);
    }
    o[0] = hsum2(a0); o[1] = hsum2(a1); o[2] = hsum2(a2); o[3] = hsum2(a3);
}

// ---------------- premask weights into SMEM ----------------
template<int HLOC, int K, int KP>
__device__ void load_weights(float* sW, float* sB, const Params& p, int l, int rowoff, int tid) {
    const float* Ws[4] = { p.W1[l], p.W2[l], p.Wa[l], p.Wb[l] };
    const float* Bs[4] = { p.b1[l], p.b2[l], p.ba[l], p.bb[l] };
    const float* M = p.m[l];
    for (int mat = 0; mat < 4; ++mat) {
        const float* W = Ws[mat];
        for (int idx = tid; idx < HLOC * KP; idx += NT) {
            int j = idx / KP;
            int k = idx - j * KP;
            float v = 0.0f;
            if (k < K) {
                int gi = (rowoff + j) * K + k;
                v = W[gi] * M[gi];
            }
            sW[mat * HLOC * KP + idx] = v;
        }
        for (int j = tid; j < HLOC; j += NT)
            sB[mat * HLOC + j] = Bs[mat][rowoff + j];
    }
}

// ---------------- stage 0: layer 0 ----------------
__device__ void run_stage0(const Params& p, int g, float* smf, uint32_t smu, int tid) {
    float* sW   = smf + STAGE_F;
    float* sB   = sW + 4 * H0 * KP0;
    float* sZ   = sB + 4 * H0;
    float* sAcc = sZ + 4 * KP0;          // 32 * 80 floats

    load_weights<H0, K0, KP0>(sW, sB, p, 0, 0, tid);
    for (int i = tid; i < 4 * KP0; i += NT) sZ[i] = 0.f;
    __syncthreads();
    for (int i = tid; i < 4 * H0; i += NT) {
        int r = i / H0, j = i - r * H0;
        sZ[r * KP0 + NF + j] = p.h0[(size_t)(g * 4 + r) * 256 + j];
    }
    __syncthreads();

    // unit mapping: units 0..307 = (halfA,row), 308..511 = (halfB,row 0..203),
    // extra units (halfB rows 204..307) on threads 0..103
    const int uhalf = (tid < 308) ? 0 : 1;
    const int urow  = uhalf ? (tid - 308) : tid;
    const int um    = urow / H0, uj = urow - um * H0;
    const float* wb = sW + urow * KP0 + (uhalf ? KA0 : 0);
    u64 wreg[RKC / 2];
    #pragma unroll
    for (int c = 0; c < RKC / 2; ++c) wreg[c] = *(const u64*)(wb + 2 * c);
    const float* wsm = wb + RKC;
    const int has_extra = (tid < 104);
    const int xrow = 204 + tid;                       // valid if has_extra
    const int xm = has_extra ? xrow / H0 : 0;
    const int xj = has_extra ? xrow - xm * H0 : 0;
    const float* wsx = sW + xrow * KP0 + KA0;         // RK=0 path

    const int er = (tid < 308) ? tid / H0 : 0;        // epilogue mapping
    const int ej = (tid < 308) ? tid - er * H0 : 0;
    const int xr2 = tid >> 6, xi = tid & 63;          // x mapping (tid<256)
    const float* xb = p.x + (size_t)(g * 4 + (xr2 & 3)) * NTIME * NF + xi;
    float xv = (tid < 256) ? xb[0] : 0.f;

    cluster_sync_all();

    const uint32_t fl_c01  = smu + FLAG_BYTE(0);
    const uint32_t r1_ring = mapa_u32(smu + RING_BYTE, 1);
    const uint32_t r1_F0   = mapa_u32(smu + FLAG_BYTE(0), 1);

    for (int t = 0; t < NTIME; ++t) {
        if (tid == 0 && t >= DEPTH) wait_flag(fl_c01, (unsigned)(t + 1 - DEPTH));
        __syncthreads();
        if (tid < 256) {
            sZ[xr2 * KP0 + xi] = xv;
            if (t + 1 < NTIME) xv = xb[(size_t)(t + 1) * NF];
        }
        __syncthreads();
        {
            float o[4];
            if (uhalf == 0) mv4r<KP0, KA0, RKC>(wsm, wreg, sZ, o);
            else            mv4r<KP0, KB0, RKC>(wsm, wreg, sZ + KA0, o);
            #pragma unroll
            for (int r = 0; r < 4; ++r) sAcc[(uhalf * 16 + um * 4 + r) * 80 + uj] = o[r];
            if (has_extra) {
                float ox[4];
                mv4r<KP0, KB0, 0>(wsx, nullptr, sZ + KA0, ox);
                #pragma unroll
                for (int r = 0; r < 4; ++r) sAcc[(16 + xm * 4 + r) * 80 + xj] = ox[r];
            }
        }
        __syncthreads();
        if (tid < 308) {
            float v[4];
            #pragma unroll
            for (int m = 0; m < 4; ++m)
                v[m] = sAcc[(m * 4 + er) * 80 + ej] + sAcc[(16 + m * 4 + er) * 80 + ej]
                     + sB[m * H0 + ej];
            float h = cfc_h(v[0], v[1], v[2], v[3]);
            sZ[er * KP0 + NF + ej] = h;
            st_remote_f32(r1_ring + (uint32_t)((((t & (DEPTH - 1)) * 320) + er * 80 + ej) * 4), h);
        }
        __syncthreads();
        if (tid == 0) { fence_cluster_acqrel(); st_flag_release(r1_F0, (unsigned)(t + 1)); }
    }
    if (p.out_size >= NB * NTIME * 128 + NB * 256 && tid < 308) {
        float* hx = p.out + (size_t)NB * NTIME * 128;
        hx[(size_t)(g * 4 + er) * 256 + ej] = sZ[er * KP0 + NF + ej];
    }
}

// ---------------- stage 1: layer 1 ----------------
__device__ void run_stage1(const Params& p, int g, float* smf, uint32_t smu, int tid) {
    float* sW   = smf + STAGE_F;
    float* sB   = sW + 4 * H1 * KP1;
    float* sZ   = sB + 4 * H1;
    float* sAcc = sZ + 4 * KP1;          // 32 * 56 floats
    float* ring01 = smf + 128;           // byte 512

    load_weights<H1, K1, KP1>(sW, sB, p, 1, 0, tid);
    for (int i = tid; i < 4 * KP1; i += NT) sZ[i] = 0.f;
    __syncthreads();
    for (int i = tid; i < 4 * H1; i += NT) {
        int r = i / H1, j = i - r * H1;
        sZ[r * KP1 + H0 + j] = p.h0[(size_t)(g * 4 + r) * 256 + H0 + j];
    }
    __syncthreads();

    const int has_unit = (tid < 408);
    const int uhalf = (tid < 204) ? 0 : 1;
    const int urow  = has_unit ? (uhalf ? tid - 204 : tid) : 0;
    const int um    = urow / H1, uj = urow - um * H1;
    const float* wb = sW + urow * KP1 + (uhalf ? KA1 : 0);
    u64 wreg[RKC / 2];
    #pragma unroll
    for (int c = 0; c < RKC / 2; ++c) wreg[c] = *(const u64*)(wb + 2 * c);
    const float* wsm = wb + RKC;

    const int cr = (tid < 308) ? tid / H0 : 0;        // copy-in mapping
    const int cj = (tid < 308) ? tid - cr * H0 : 0;
    const int er = (tid < 204) ? tid / H1 : 0;        // epilogue mapping
    const int ej = (tid < 204) ? tid - er * H1 : 0;

    cluster_sync_all();

    const uint32_t fl_p0  = smu + FLAG_BYTE(0);
    const uint32_t fl_c2a = smu + FLAG_BYTE(1);
    const uint32_t fl_c2b = smu + FLAG_BYTE(2);
    const uint32_t r0_F0  = mapa_u32(smu + FLAG_BYTE(0), 0);
    const uint32_t r2_ring = mapa_u32(smu + RING_BYTE, 2);
    const uint32_t r3_ring = mapa_u32(smu + RING_BYTE, 3);
    const uint32_t r2_F0  = mapa_u32(smu + FLAG_BYTE(0), 2);
    const uint32_t r3_F0  = mapa_u32(smu + FLAG_BYTE(0), 3);

    for (int t = 0; t < NTIME; ++t) {
        if (tid == 0)                     wait_flag(fl_p0,  (unsigned)(t + 1));
        else if (tid == 32 && t >= DEPTH) wait_flag(fl_c2a, (unsigned)(t + 1 - DEPTH));
        else if (tid == 64 && t >= DEPTH) wait_flag(fl_c2b, (unsigned)(t + 1 - DEPTH));
        __syncthreads();
        if (tid < 308) {
            const float* islot = ring01 + (t & (DEPTH - 1)) * 320;
            sZ[cr * KP1 + cj] = islot[cr * 80 + cj];
        }
        __syncthreads();
        if (tid == 0) st_flag_release(r0_F0, (unsigned)(t + 1));
        if (has_unit) {
            float o[4];
            if (uhalf == 0) mv4r<KP1, KA1, RKC>(wsm, wreg, sZ, o);
            else            mv4r<KP1, KB1, RKC>(wsm, wreg, sZ + KA1, o);
            #pragma unroll
            for (int r = 0; r < 4; ++r) sAcc[(uhalf * 16 + um * 4 + r) * 56 + uj] = o[r];
        }
        __syncthreads();
        if (tid < 204) {
            float v[4];
            #pragma unroll
            for (int m = 0; m < 4; ++m)
                v[m] = sAcc[(m * 4 + er) * 56 + ej] + sAcc[(16 + m * 4 + er) * 56 + ej]
                     + sB[m * H1 + ej];
            float h = cfc_h(v[0], v[1], v[2], v[3]);
            sZ[er * KP1 + H0 + ej] = h;
            uint32_t off = (uint32_t)((((t & (DEPTH - 1)) * 224) + er * 56 + ej) * 4);
            st_remote_f32(r2_ring + off, h);
            st_remote_f32(r3_ring + off, h);
        }
        __syncthreads();
        if (tid == 0) {
            fence_cluster_acqrel();
            st_flag_release(r2_F0, (unsigned)(t + 1));
            st_flag_release(r3_F0, (unsigned)(t + 1));
        }
    }
    if (p.out_size >= NB * NTIME * 128 + NB * 256 && tid < 204) {
        float* hx = p.out + (size_t)NB * NTIME * 128;
        hx[(size_t)(g * 4 + er) * 256 + H0 + ej] = sZ[er * KP1 + H0 + ej];
    }
}

// ---------------- stage 2: layer 2 half ----------------
template<int HALF>
__device__ void run_stage2(const Params& p, int g, float* smf, uint32_t smu, int tid) {
    float* sW   = smf + STAGE_F;
    float* sB   = sW + 4 * H2H * KP2;
    float* sZ   = sB + 4 * H2H;
    float* sAcc = sZ + 4 * KP2;          // 32 * 64 floats
    float* ring12   = smf + 128;                  // byte 512
    float* ringPeer = smf + 128 + DEPTH * 224;    // byte 7680

    const int IN = H1;                            // 51
    const int zoff  = IN + HALF * 64;
    const int zpeer = IN + (1 - HALF) * 64;
    const int peer_rank = HALF ? 2 : 3;

    load_weights<H2H, K2, KP2>(sW, sB, p, 2, HALF * 64, tid);
    for (int i = tid; i < 4 * KP2; i += NT) sZ[i] = 0.f;
    __syncthreads();
    for (int i = tid; i < 4 * H2; i += NT) {
        int r = i >> 7, u = i & 127;
        sZ[r * KP2 + IN + u] = p.h0[(size_t)(g * 4 + r) * 256 + 128 + u];
    }
    __syncthreads();

    const int uhalf = tid >> 8;                   // warps 0-7 A, 8-15 B
    const int urow  = tid & 255;
    const int um    = urow >> 6, uj = urow & 63;
    const float* wb = sW + urow * KP2 + (uhalf ? KA2 : 0);
    u64 wreg[RKC / 2];
    #pragma unroll
    for (int c = 0; c < RKC / 2; ++c) wreg[c] = *(const u64*)(wb + 2 * c);
    const float* wsm = wb + RKC;

    const int cr = (tid < 204) ? tid / IN : 0;    // ring12 copy mapping
    const int cj = (tid < 204) ? tid - cr * IN : 0;
    const int r2 = (tid & 255) >> 6, j2 = tid & 63;   // epilogue / peer-copy mapping

    cluster_sync_all();

    const uint32_t fl_p1 = smu + FLAG_BYTE(0);    // rank1 produced
    const uint32_t fl_pp = smu + FLAG_BYTE(1);    // peer produced into my ringPeer
    const uint32_t fl_pc = smu + FLAG_BYTE(2);    // peer consumed my pushes
    const uint32_t r1_Fc = mapa_u32(smu + FLAG_BYTE(1 + HALF), 1);
    const uint32_t pr_F1 = mapa_u32(smu + FLAG_BYTE(1), (uint32_t)peer_rank);
    const uint32_t pr_F2 = mapa_u32(smu + FLAG_BYTE(2), (uint32_t)peer_rank);
    const uint32_t pr_ringP = mapa_u32(smu + RINGP_BYTE, (uint32_t)peer_rank);

    for (int t = 0; t < NTIME; ++t) {
        if (tid == 0)                     wait_flag(fl_p1, (unsigned)(t + 1));
        else if (tid == 32 && t >= 1)     wait_flag(fl_pp, (unsigned)t);
        else if (tid == 64 && t >= DEPTH) wait_flag(fl_pc, (unsigned)(t + 1 - DEPTH));
        __syncthreads();
        if (tid < 204) {
            const float* islot = ring12 + (t & (DEPTH - 1)) * 224;
            sZ[cr * KP2 + cj] = islot[cr * 56 + cj];
        }
        if (tid >= 256 && t >= 1) {
            int q = tid - 256;
            const float* ps = ringPeer + ((t - 1) & (DEPTH - 1)) * 256;
            sZ[(q >> 6) * KP2 + zpeer + (q & 63)] = ps[q];
        }
        __syncthreads();
        if (tid == 0) {
            st_flag_release(r1_Fc, (unsigned)(t + 1));
            if (t >= 1) st_flag_release(pr_F2, (unsigned)t);
        }
        {
            float o[4];
            if (uhalf == 0) mv4r<KP2, KA2, RKC>(wsm, wreg, sZ, o);
            else            mv4r<KP2, KB2, RKC>(wsm, wreg, sZ + KA2, o);
            #pragma unroll
            for (int r = 0; r < 4; ++r) sAcc[(uhalf * 16 + um * 4 + r) * 64 + uj] = o[r];
        }
        __syncthreads();
        if (tid < 256) {
            float v[4];
            #pragma unroll
            for (int m = 0; m < 4; ++m)
                v[m] = sAcc[(m * 4 + r2) * 64 + j2] + sAcc[(16 + m * 4 + r2) * 64 + j2]
                     + sB[m * H2H + j2];
            float h = cfc_h(v[0], v[1], v[2], v[3]);
            sZ[r2 * KP2 + zoff + j2] = h;
            st_remote_f32(pr_ringP + (uint32_t)((((t & (DEPTH - 1)) * 256) + r2 * 64 + j2) * 4), h);
            p.out[((size_t)(g * 4 + r2) * NTIME + t) * 128 + HALF * 64 + j2] = h;
        }
        __syncthreads();
        if (tid == 0) { fence_cluster_acqrel(); st_flag_release(pr_F1, (unsigned)(t + 1)); }
    }
    if (p.out_size >= NB * NTIME * 128 + NB * 256 && tid < 256) {
        float* hx = p.out + (size_t)NB * NTIME * 128;
        hx[(size_t)(g * 4 + r2) * 256 + 128 + HALF * 64 + j2] = sZ[r2 * KP2 + zoff + j2];
    }
}

// ---------------- kernel ----------------
__global__ void __launch_bounds__(NT, 1) cfc_kernel(Params p) {
    extern __shared__ unsigned char smraw[];
    float* smf = (float*)smraw;
    const uint32_t smu = smem_addr_u32(smraw);
    const int stage = blockIdx.x & 3;
    const int g     = blockIdx.x >> 2;
    const int tid   = threadIdx.x;

    if (tid < 16) *(unsigned*)(smraw + FLAG_BYTE(tid)) = 0u;   // fresh flags per launch

    if      (stage == 0) run_stage0(p, g, smf, smu, tid);
    else if (stage == 1) run_stage1(p, g, smf, smu, tid);
    else if (stage == 2) run_stage2<0>(p, g, smf, smu, tid);
    else                 run_stage2<1>(p, g, smf, smu, tid);

    cluster_sync_all();   // no CTA exits while peers may still push into its smem
}

// ---------------- host launch ----------------
extern "C" void kernel_launch(void* const* d_in, const int* in_sizes, int n_in,
                              void* d_out, int out_size) {
    Params p;
    p.x  = (const float*)d_in[0];
    p.h0 = (const float*)d_in[1];
    bool sig_order = (n_in > 4 && in_sizes[4] == 77);
    for (int l = 0; l < 3; ++l) {
        int b = 2 + 9 * l;
        p.m[l] = (const float*)d_in[b];
        if (!sig_order) {
            p.W1[l] = (const float*)d_in[b + 1];
            p.W2[l] = (const float*)d_in[b + 2];
            p.Wa[l] = (const float*)d_in[b + 3];
            p.Wb[l] = (const float*)d_in[b + 4];
            p.b1[l] = (const float*)d_in[b + 5];
            p.b2[l] = (const float*)d_in[b + 6];
            p.ba[l] = (const float*)d_in[b + 7];
            p.bb[l] = (const float*)d_in[b + 8];
        } else {
            p.W1[l] = (const float*)d_in[b + 1];
            p.b1[l] = (const float*)d_in[b + 2];
            p.W2[l] = (const float*)d_in[b + 3];
            p.b2[l] = (const float*)d_in[b + 4];
            p.Wa[l] = (const float*)d_in[b + 5];
            p.ba[l] = (const float*)d_in[b + 6];
            p.Wb[l] = (const float*)d_in[b + 7];
            p.bb[l] = (const float*)d_in[b + 8];
        }
    }
    p.out = (float*)d_out;
    p.out_size = out_size;

    cudaFuncSetAttribute(cfc_kernel, cudaFuncAttributeMaxDynamicSharedMemorySize, SMEM_BYTES);

    cudaLaunchConfig_t cfg = {};
    cfg.gridDim  = dim3(4 * NG, 1, 1);
    cfg.blockDim = dim3(NT, 1, 1);
    cfg.dynamicSmemBytes = SMEM_BYTES;
    cfg.stream = 0;
    cudaLaunchAttribute attr[1];
    attr[0].id = cudaLaunchAttributeClusterDimension;
    attr[0].val.clusterDim.x = 4;
    attr[0].val.clusterDim.y = 1;
    attr[0].val.clusterDim.z = 1;
    cfg.attrs = attr;
    cfg.numAttrs = 1;
    cudaLaunchKernelEx(&cfg, cfc_kernel, p);
}